// round 3
// baseline (speedup 1.0000x reference)
#include <cuda_runtime.h>
#include <math.h>

#define NTHREADS 256
#define BK 32

typedef unsigned long long ull;

// ---- packed f32x2 helpers (sm_103a: fma.rn.f32x2 doubles FFMA issue rate) ----
__device__ __forceinline__ ull pack2(float lo, float hi) {
    ull r;
    asm("mov.b64 %0, {%1, %2};" : "=l"(r) : "f"(lo), "f"(hi));
    return r;
}
__device__ __forceinline__ void unpack2(ull v, float& lo, float& hi) {
    asm("mov.b64 {%0, %1}, %2;" : "=f"(lo), "=f"(hi) : "l"(v));
}
__device__ __forceinline__ void fma2(ull& acc, ull a, ull b) {
    asm("fma.rn.f32x2 %0, %1, %2, %0;" : "+l"(acc) : "l"(a), "l"(b));
}

// One CTA per (b, t) 128-token compression block.
//   GEMM: [128 tokens x H] @ [H x 256]  (256 = kv|gate concatenated)
//   warp wg (0..7): output columns [wg*16, wg*16+16) of each matrix
//   lane tm (0..31): output rows [tm*4, tm*4+4)
// Then: column softmax over the 128 rows, weighted sum, RMS norm, RoPE.
__global__ void __launch_bounds__(NTHREADS, 1)
hca_fused_kernel(const float* __restrict__ hs,
                 const int*   __restrict__ pos_ids,
                 const float* __restrict__ w_kv,
                 const float* __restrict__ w_gate,
                 const float* __restrict__ bias,
                 const float* __restrict__ norm_w,
                 float*       __restrict__ out,
                 int H)
{
    // 48 KB static smem: As[32][128] (A^T: [k][m]) + Ws[32][256]
    __shared__ __align__(16) float smem[BK * 128 + BK * 256];
    float* As = smem;
    float* Ws = smem + BK * 128;

    const int tid = threadIdx.x;
    const int wg  = tid >> 5;   // n-group (0..7)
    const int tm  = tid & 31;   // m-group: rows tm*4..tm*4+3

    const float* hblk = hs + (size_t)blockIdx.x * 128 * (size_t)H;

    ull acc_kv[4][8];   // [row j][col-pair p]  cols wg*16 + 2p, 2p+1
    ull acc_g [4][8];
    #pragma unroll
    for (int j = 0; j < 4; ++j)
        #pragma unroll
        for (int p = 0; p < 8; ++p) { acc_kv[j][p] = 0ull; acc_g[j][p] = 0ull; }

    const int nchunks = H >> 5;
    for (int kc = 0; kc < nchunks; ++kc) {
        const int k0 = kc << 5;
        __syncthreads();
        // A tile: 128 rows x 32 k, transposed into As[k][m]. Coalesced float4 gmem.
        #pragma unroll
        for (int i = 0; i < 4; ++i) {
            int flat = tid + i * 256;          // 0..1023
            int row  = flat >> 3;              // 0..127
            int c4   = (flat & 7) << 2;        // 0,4,..,28
            float4 v = *(const float4*)(hblk + (size_t)row * H + (k0 + c4));
            As[(c4 + 0) * 128 + row] = v.x;
            As[(c4 + 1) * 128 + row] = v.y;
            As[(c4 + 2) * 128 + row] = v.z;
            As[(c4 + 3) * 128 + row] = v.w;
        }
        // W tile: 32 k x 256 n (kv cols 0..127, gate cols 128..255)
        #pragma unroll
        for (int i = 0; i < 8; ++i) {
            int flat = tid + i * 256;          // 0..2047
            int k    = flat >> 6;              // 0..31
            int n4   = flat & 63;              // float4 group
            const float* src = (n4 < 32)
                ? (w_kv   + (size_t)(k0 + k) * 128 + (n4 << 2))
                : (w_gate + (size_t)(k0 + k) * 128 + ((n4 - 32) << 2));
            *(float4*)&Ws[k * 256 + (n4 << 2)] = *(const float4*)src;
        }
        __syncthreads();

        #pragma unroll 2
        for (int k = 0; k < BK; ++k) {
            float4 a4 = *(const float4*)&As[k * 128 + tm * 4];
            ull a2[4];
            a2[0] = pack2(a4.x, a4.x);
            a2[1] = pack2(a4.y, a4.y);
            a2[2] = pack2(a4.z, a4.z);
            a2[3] = pack2(a4.w, a4.w);
            const ull* wk2 = (const ull*)&Ws[k * 256 + wg * 16];        // broadcast
            const ull* wg2 = (const ull*)&Ws[k * 256 + 128 + wg * 16];  // broadcast
            #pragma unroll
            for (int p = 0; p < 8; ++p) {
                ull bkv = wk2[p];
                ull bg  = wg2[p];
                #pragma unroll
                for (int j = 0; j < 4; ++j) {
                    fma2(acc_kv[j][p], a2[j], bkv);
                    fma2(acc_g [j][p], a2[j], bg);
                }
            }
        }
    }
    __syncthreads();

    // ---- epilogue (GEMM smem is dead; overlay small arrays) ----
    float* comp_s = smem;          // 128: compressed[d]
    float* ss_s   = smem + 128;    // 8:   per-warp sum of squares
    float* cn_s   = smem + 160;    // 128: normalized compressed

    // Per column d: S1 = sum_r exp(gate+bias), S2 = sum_r exp(..)*kv.
    // No max-subtraction: |gate+bias| <~ 5, exp is safe in fp32 and
    // S2/S1 is algebraically identical to softmax-weighted sum.
    float ss = 0.f;
    #pragma unroll
    for (int c = 0; c < 16; ++c) {
        const int d = wg * 16 + c;
        const int p = c >> 1;
        float s1 = 0.f, s2 = 0.f;
        #pragma unroll
        for (int j = 0; j < 4; ++j) {
            int row = tm * 4 + j;
            float kl, kh, gl, gh;
            unpack2(acc_kv[j][p], kl, kh);
            unpack2(acc_g [j][p], gl, gh);
            float kv = (c & 1) ? kh : kl;
            float g  = ((c & 1) ? gh : gl) + __ldg(&bias[row * 128 + d]);
            float e  = expf(g);
            s1 += e;
            s2 += e * kv;
        }
        #pragma unroll
        for (int off = 16; off > 0; off >>= 1) {
            s1 += __shfl_xor_sync(0xffffffffu, s1, off);
            s2 += __shfl_xor_sync(0xffffffffu, s2, off);
        }
        float comp = s2 / s1;
        if (tm == c) comp_s[d] = comp;
        ss += comp * comp;          // same value in every lane
    }
    if (tm == 0) ss_s[wg] = ss;
    __syncthreads();

    // RMS norm over d=128
    if (tid < 128) {
        float tot = 0.f;
        #pragma unroll
        for (int i = 0; i < 8; ++i) tot += ss_s[i];
        float inv = rsqrtf(tot * (1.0f / 128.0f) + 1e-6f);
        cn_s[tid] = comp_s[tid] * inv * __ldg(&norm_w[tid]);
    }
    __syncthreads();

    // RoPE on last 64 dims; replicate the reference's fp32 rounding:
    //   inv_freq = 1/fp32(10000^(i/32));  freq = fp32(pos * inv_freq);
    // then near-exact cos/sin of that fp32 angle via double.
    if (tid < 128) {
        const int d = tid;
        float o;
        if (d < 64) {
            o = cn_s[d];
        } else {
            int jj = d - 64;
            int ii = jj >> 1;
            float posf = (float)__ldg(&pos_ids[(size_t)blockIdx.x * 128]);
            double pw  = pow(10000.0, (double)ii * (1.0 / 32.0));
            float invf = 1.0f / (float)pw;
            float freq = posf * invf;
            double a   = (double)freq;
            float cs = (float)cos(a);
            float sn = (float)sin(a);
            float r  = cn_s[d];
            float rh = (jj < 32) ? -cn_s[d + 32] : cn_s[d - 32];
            o = r * cs + rh * sn;
        }
        out[(size_t)blockIdx.x * 128 + d] = o;
    }
}

extern "C" void kernel_launch(void* const* d_in, const int* in_sizes, int n_in,
                              void* d_out, int out_size) {
    (void)n_in;
    const float* hs   = (const float*)d_in[0];   // hidden_states (B,S,H) f32
    const int*   pid  = (const int*)  d_in[2];   // position_ids (B,S) i32
    const float* wkv  = (const float*)d_in[3];   // (H,128)
    const float* wgt  = (const float*)d_in[4];   // (H,128)
    const float* bias = (const float*)d_in[5];   // (128,128)
    const float* nw   = (const float*)d_in[6];   // (128,)
    float* out = (float*)d_out;                  // (B,1,T,128) f32

    int H    = in_sizes[3] / 128;                // 2048
    int nblk = out_size / 128;                   // B*T = 128

    hca_fused_kernel<<<nblk, NTHREADS>>>(hs, pid, wkv, wgt, bias, nw, out, H);
}

// round 7
// speedup vs baseline: 2.8547x; 2.8547x over previous
#include <cuda_runtime.h>
#include <cuda_bf16.h>
#include <stdint.h>
#include <math.h>

#define NTHREADS 256
#define MAXCHUNKS 32
#define KC 64

// Prepped weights: [split hi/lo][chunk][k(64)][n(256)] bf16, linear (swizzle applied at cp.async dst)
__device__ __align__(16) unsigned char g_Bpre[2u * MAXCHUNKS * KC * 256 * 2];  // 2 MB

// ---- dynamic smem layout (bytes) ----
#define ARAW   0                      // 2 stages x 32768 (A raw fp32 128x64)
#define ATIL   65536                  // 2 splits x 16384 (A bf16 tiles 128x64)
#define BST    98304                  // 2 stages x 65536 (B: hi 32768 + lo 32768, swizzled)
#define SMEM_TOTAL 229376
// epilogue overlays (everything above is dead by then)
#define EP_P1   131072
#define EP_P2   132096
#define EP_COMP 133120
#define EP_CN   133632
#define EP_SSW  134144

static __device__ __forceinline__ uint32_t smem_u32(const void* p) {
    uint32_t a;
    asm("{ .reg .u64 t; cvta.to.shared.u64 t, %1; cvt.u32.u64 %0, t; }" : "=r"(a) : "l"(p));
    return a;
}
static __device__ __forceinline__ uint32_t cvt2(float hi, float lo) {
    uint32_t r;
    asm("cvt.rn.bf16x2.f32 %0, %1, %2;" : "=r"(r) : "f"(hi), "f"(lo));
    return r;
}
static __device__ __forceinline__ void cp16(uint32_t dst, const void* src) {
    asm volatile("cp.async.cg.shared.global [%0], [%1], 16;" :: "r"(dst), "l"(src));
}
#define CP_COMMIT() asm volatile("cp.async.commit_group;" ::: "memory")
#define CP_WAIT1()  asm volatile("cp.async.wait_group 1;" ::: "memory")

#define LDMX4(r, a) \
    asm volatile("ldmatrix.sync.aligned.m8n8.x4.shared.b16 {%0,%1,%2,%3}, [%4];" \
        : "=r"((r)[0]), "=r"((r)[1]), "=r"((r)[2]), "=r"((r)[3]) : "r"(a))
#define LDMX4T(r, a) \
    asm volatile("ldmatrix.sync.aligned.m8n8.x4.trans.shared.b16 {%0,%1,%2,%3}, [%4];" \
        : "=r"((r)[0]), "=r"((r)[1]), "=r"((r)[2]), "=r"((r)[3]) : "r"(a))
#define MMA16816(c, a, b0, b1) \
    asm volatile("mma.sync.aligned.m16n8k16.row.col.f32.bf16.bf16.f32 " \
        "{%0,%1,%2,%3},{%4,%5,%6,%7},{%8,%9},{%0,%1,%2,%3};" \
        : "+f"((c)[0]), "+f"((c)[1]), "+f"((c)[2]), "+f"((c)[3]) \
        : "r"((a)[0]), "r"((a)[1]), "r"((a)[2]), "r"((a)[3]), "r"(b0), "r"(b1))

// ---------------- prep: weights -> bf16 hi/lo split images ----------------
__global__ void prep_b_kernel(const float* __restrict__ wkv, const float* __restrict__ wgate,
                              int nchunks) {
    int idx = blockIdx.x * blockDim.x + threadIdx.x;
    if (idx >= nchunks * 64 * 64) return;
    int n4 = idx & 63;           // group of 4 n-columns (n = n4*4, 0..255)
    int k  = (idx >> 6) & 63;    // k within chunk
    int c  = idx >> 12;          // chunk
    int kg = c * 64 + k;
    int n  = n4 * 4;
    const float* w = (n < 128) ? (wkv + (size_t)kg * 128 + n)
                               : (wgate + (size_t)kg * 128 + (n - 128));
    float x0 = w[0], x1 = w[1], x2 = w[2], x3 = w[3];
    uint32_t h0 = cvt2(x1, x0), h1 = cvt2(x3, x2);
    float r0 = x0 - __uint_as_float(h0 << 16);
    float r1 = x1 - __uint_as_float(h0 & 0xFFFF0000u);
    float r2 = x2 - __uint_as_float(h1 << 16);
    float r3 = x3 - __uint_as_float(h1 & 0xFFFF0000u);
    uint32_t l0 = cvt2(r1, r0), l1 = cvt2(r3, r2);
    size_t off = (size_t)c * 32768 + (size_t)k * 512 + (size_t)n * 2;
    *(uint2*)(g_Bpre + off) = make_uint2(h0, h1);
    *(uint2*)(g_Bpre + (size_t)nchunks * 32768 + off) = make_uint2(l0, l1);
}

// ---------------- main fused kernel ----------------
__global__ void __launch_bounds__(NTHREADS, 1)
hca_mma_kernel(const float* __restrict__ hs,
               const int*   __restrict__ pos_ids,
               const float* __restrict__ bias,
               const float* __restrict__ norm_w,
               float*       __restrict__ out,
               int H, int nchunks)
{
    extern __shared__ __align__(16) unsigned char sm[];
    const uint32_t smb = smem_u32(sm);

    const int tid   = threadIdx.x;
    const int wid   = tid >> 5;
    const int lane  = tid & 31;
    const int mwarp = wid >> 2;   // 0..1 -> rows mwarp*64
    const int nwarp = wid & 3;    // 0..3 -> cols nwarp*64

    const float* hblk = hs + (size_t)blockIdx.x * 128 * (size_t)H;
    const size_t bLoOff = (size_t)nchunks * 32768;

    // ---- cp.async issue helpers ----
    // A raw fp32 chunk (128x64): 2048 16B units; 8 per thread, linear dst
    // B chunk: per split 2048 16B units (64 rows x 512B); swizzle at dst
    #define ISSUE_A(c_, s_) do { \
        const int k0_ = (c_) * KC; \
        _Pragma("unroll") \
        for (int i_ = 0; i_ < 8; ++i_) { \
            int u_ = tid + i_ * NTHREADS; \
            int row_ = u_ >> 4, jb_ = u_ & 15; \
            cp16(smb + ARAW + (s_) * 32768 + u_ * 16, \
                 hblk + (size_t)row_ * H + k0_ + jb_ * 4); \
        } \
    } while (0)
    #define ISSUE_B(c_, s_) do { \
        _Pragma("unroll") \
        for (int i_ = 0; i_ < 8; ++i_) { \
            int u_ = tid + i_ * NTHREADS; \
            int k_ = u_ >> 5, j_ = u_ & 31; \
            uint32_t doff_ = (uint32_t)k_ * 512 + (uint32_t)((j_ ^ (k_ & 7)) << 4); \
            const unsigned char* srcH_ = g_Bpre + (size_t)(c_) * 32768 + (size_t)u_ * 16; \
            cp16(smb + BST + (s_) * 65536 + doff_, srcH_); \
            cp16(smb + BST + (s_) * 65536 + 32768 + doff_, srcH_ + bLoOff); \
        } \
    } while (0)

    ISSUE_A(0, 0); ISSUE_B(0, 0); CP_COMMIT();
    ISSUE_A(1, 1); ISSUE_B(1, 1); CP_COMMIT();

    float acc[4][8][4];
    #pragma unroll
    for (int mi = 0; mi < 4; ++mi)
        #pragma unroll
        for (int ni = 0; ni < 8; ++ni)
            #pragma unroll
            for (int e = 0; e < 4; ++e) acc[mi][ni][e] = 0.f;

    // per-lane ldmatrix address bases
    const uint32_t keyA  = lane & 7;
    const uint32_t aRow  = (uint32_t)(mwarp * 64 + (lane & 7) + ((lane >> 3) & 1) * 8) * 128;
    const uint32_t aHalf = lane >> 4;
    const uint32_t bKlo  = (lane & 7) + ((lane >> 3) & 1) * 8;     // k within k16
    const uint32_t bNb   = (uint32_t)(nwarp * 8 + (lane >> 4));    // 16B n-block base
    const uint32_t atB   = smb + ATIL;

    for (int c = 0; c < nchunks; ++c) {
        const int s = c & 1;
        CP_WAIT1();
        __syncthreads();

        // split-convert A raw fp32 -> bf16 hi/lo swizzled tiles
        {
            const float4* ar = (const float4*)(sm + ARAW + s * 32768);
            #pragma unroll
            for (int i = 0; i < 8; ++i) {
                int u = tid + i * NTHREADS;
                int row = u >> 4, jb = u & 15;
                float4 x = ar[u];
                uint32_t h0 = cvt2(x.y, x.x), h1 = cvt2(x.w, x.z);
                float r0 = x.x - __uint_as_float(h0 << 16);
                float r1 = x.y - __uint_as_float(h0 & 0xFFFF0000u);
                float r2 = x.z - __uint_as_float(h1 << 16);
                float r3 = x.w - __uint_as_float(h1 & 0xFFFF0000u);
                uint32_t l0 = cvt2(r1, r0), l1 = cvt2(r3, r2);
                uint32_t off = (uint32_t)row * 128 + (uint32_t)(((jb >> 1) ^ (row & 7)) << 4)
                             + (uint32_t)((jb & 1) * 8);
                *(uint2*)(sm + ATIL + off)         = make_uint2(h0, h1);
                *(uint2*)(sm + ATIL + 16384 + off) = make_uint2(l0, l1);
            }
        }
        __syncthreads();

        // compute: 4 k16 steps, 3 split-combos each
        const uint32_t bStage = smb + BST + s * 65536;
        #pragma unroll
        for (int kk = 0; kk < 4; ++kk) {
            uint32_t ah[4][4], al[4][4], bh[4][4], bl[4][4];
            const uint32_t aOff = ((kk * 2 + aHalf) ^ keyA) << 4;
            const uint32_t bRow = (uint32_t)kk * 8192 + bKlo * 512;
            #pragma unroll
            for (int mi = 0; mi < 4; ++mi)
                LDMX4(ah[mi], atB + aRow + mi * 2048 + aOff);
            #pragma unroll
            for (int ni2 = 0; ni2 < 4; ++ni2)
                LDMX4T(bh[ni2], bStage + bRow + (((bNb + ni2 * 2) ^ keyA) << 4));
            #pragma unroll
            for (int mi = 0; mi < 4; ++mi)
                #pragma unroll
                for (int ni2 = 0; ni2 < 4; ++ni2) {
                    MMA16816(acc[mi][ni2 * 2],     ah[mi], bh[ni2][0], bh[ni2][1]);
                    MMA16816(acc[mi][ni2 * 2 + 1], ah[mi], bh[ni2][2], bh[ni2][3]);
                }
            #pragma unroll
            for (int ni2 = 0; ni2 < 4; ++ni2)
                LDMX4T(bl[ni2], bStage + 32768 + bRow + (((bNb + ni2 * 2) ^ keyA) << 4));
            #pragma unroll
            for (int mi = 0; mi < 4; ++mi)
                #pragma unroll
                for (int ni2 = 0; ni2 < 4; ++ni2) {
                    MMA16816(acc[mi][ni2 * 2],     ah[mi], bl[ni2][0], bl[ni2][1]);
                    MMA16816(acc[mi][ni2 * 2 + 1], ah[mi], bl[ni2][2], bl[ni2][3]);
                }
            #pragma unroll
            for (int mi = 0; mi < 4; ++mi)
                LDMX4(al[mi], atB + 16384 + aRow + mi * 2048 + aOff);
            #pragma unroll
            for (int mi = 0; mi < 4; ++mi)
                #pragma unroll
                for (int ni2 = 0; ni2 < 4; ++ni2) {
                    MMA16816(acc[mi][ni2 * 2],     al[mi], bh[ni2][0], bh[ni2][1]);
                    MMA16816(acc[mi][ni2 * 2 + 1], al[mi], bh[ni2][2], bh[ni2][3]);
                }
        }
        __syncthreads();

        if (c + 2 < nchunks) { ISSUE_A(c + 2, s); ISSUE_B(c + 2, s); }
        CP_COMMIT();
    }

    // ---------------- epilogue ----------------
    // Dump accums to bank-swizzled smem matrix: val(r, col) at byte
    //   r*1024 + (((col>>1) ^ (r&7)) << 3) + (col&1)*4
    #pragma unroll
    for (int mi = 0; mi < 4; ++mi) {
        int row0 = mwarp * 64 + mi * 16 + (lane >> 2);
        int row1 = row0 + 8;
        #pragma unroll
        for (int ni = 0; ni < 8; ++ni) {
            int pair = nwarp * 32 + ni * 4 + (lane & 3);
            *(float2*)(sm + row0 * 1024 + ((pair ^ (row0 & 7)) << 3)) =
                make_float2(acc[mi][ni][0], acc[mi][ni][1]);
            *(float2*)(sm + row1 * 1024 + ((pair ^ (row1 & 7)) << 3)) =
                make_float2(acc[mi][ni][2], acc[mi][ni][3]);
        }
    }
    __syncthreads();

    // softmax-weighted column reduction (validated round-2 math):
    // S1 = sum_r exp(gate+bias), S2 = sum_r exp(..)*kv ; comp = S2/S1
    {
        const int d = tid & 127, half = tid >> 7;
        float s1 = 0.f, s2 = 0.f;
        #pragma unroll 8
        for (int ri = 0; ri < 64; ++ri) {
            int r = half * 64 + ri;
            float kv = *(const float*)(sm + r * 1024 + ((((d >> 1)      ) ^ (r & 7)) << 3) + (d & 1) * 4);
            float gv = *(const float*)(sm + r * 1024 + (((64 + (d >> 1)) ^ (r & 7)) << 3) + (d & 1) * 4);
            float g = gv + __ldg(&bias[r * 128 + d]);
            float e = expf(g);
            s1 += e;
            s2 += e * kv;
        }
        ((float*)(sm + EP_P1))[half * 128 + d] = s1;
        ((float*)(sm + EP_P2))[half * 128 + d] = s2;
    }
    __syncthreads();

    if (tid < 128) {
        float* P1 = (float*)(sm + EP_P1);
        float* P2 = (float*)(sm + EP_P2);
        float s1 = P1[tid] + P1[128 + tid];
        float s2 = P2[tid] + P2[128 + tid];
        float comp = s2 / s1;
        ((float*)(sm + EP_COMP))[tid] = comp;
        float ss = comp * comp;
        #pragma unroll
        for (int o = 16; o > 0; o >>= 1) ss += __shfl_xor_sync(0xffffffffu, ss, o);
        if (lane == 0) ((float*)(sm + EP_SSW))[wid] = ss;
    }
    __syncthreads();
    if (tid < 128) {
        float* SSW = (float*)(sm + EP_SSW);
        float tot = SSW[0] + SSW[1] + SSW[2] + SSW[3];
        float inv = rsqrtf(tot * (1.0f / 128.0f) + 1e-6f);
        ((float*)(sm + EP_CN))[tid] = ((float*)(sm + EP_COMP))[tid] * inv * __ldg(&norm_w[tid]);
    }
    __syncthreads();
    if (tid < 128) {
        const float* CN = (const float*)(sm + EP_CN);
        const int d = tid;
        float o;
        if (d < 64) {
            o = CN[d];
        } else {
            int jj = d - 64;
            int ii = jj >> 1;
            float posf = (float)__ldg(&pos_ids[(size_t)blockIdx.x * 128]);
            double pw  = pow(10000.0, (double)ii * (1.0 / 32.0));
            float invf = 1.0f / (float)pw;
            float freq = posf * invf;
            double a   = (double)freq;
            float cs = (float)cos(a);
            float sn = (float)sin(a);
            float r  = CN[d];
            float rh = (jj < 32) ? -CN[d + 32] : CN[d - 32];
            o = r * cs + rh * sn;
        }
        out[(size_t)blockIdx.x * 128 + d] = o;
    }
}

extern "C" void kernel_launch(void* const* d_in, const int* in_sizes, int n_in,
                              void* d_out, int out_size) {
    (void)n_in;
    const float* hs   = (const float*)d_in[0];   // hidden_states (B,S,H) f32
    const int*   pid  = (const int*)  d_in[2];   // position_ids (B,S) i32
    const float* wkv  = (const float*)d_in[3];   // (H,128)
    const float* wgt  = (const float*)d_in[4];   // (H,128)
    const float* bias = (const float*)d_in[5];   // (128,128)
    const float* nw   = (const float*)d_in[6];   // (128,)
    float* out = (float*)d_out;

    int H       = in_sizes[3] / 128;             // 2048
    int nchunks = H / KC;                        // 32
    int nblk    = out_size / 128;                // B*T = 128

    int prep_total = nchunks * 64 * 64;
    prep_b_kernel<<<(prep_total + 255) / 256, 256>>>(wkv, wgt, nchunks);

    cudaFuncSetAttribute(hca_mma_kernel, cudaFuncAttributeMaxDynamicSharedMemorySize, SMEM_TOTAL);
    hca_mma_kernel<<<nblk, NTHREADS, SMEM_TOTAL>>>(hs, pid, bias, nw, out, H, nchunks);
}

// round 10
// speedup vs baseline: 2.8667x; 1.0042x over previous
#include <cuda_runtime.h>
#include <cuda_bf16.h>
#include <stdint.h>
#include <math.h>

#define NTHREADS 256
#define MAXCHUNKS 64
#define KC 32
#define BCHUNK 16384   // B bytes per split per chunk (32k x 256n x 2B)
#define ACHUNK 16384   // A raw bytes per chunk (128 x 32 f32)

// Prepped weights: [split hi/lo][chunk][k(32)][n(256)] bf16 (swizzle applied at cp.async dst)
__device__ __align__(16) unsigned char g_Bpre[2u * MAXCHUNKS * BCHUNK];  // 2 MB

// ---- dynamic smem layout (bytes) ----
#define BST    0                      // 3 stages x 32768 (hi 16KB + lo 16KB), swizzled
#define ARAW   98304                  // 3 stages x 16384 (A raw fp32 128x32)
#define ATIL   147456                 // 2 stages x 16384 (hi 8KB + lo 8KB), swizzled
#define SMEM_TOTAL 180224
// epilogue overlays (GEMM smem dead by then); acc dump occupies [0, 131072)
#define EP_P1   131072
#define EP_P2   132096
#define EP_COMP 133120
#define EP_CN   133632
#define EP_SSW  134144

static __device__ __forceinline__ uint32_t smem_u32(const void* p) {
    uint32_t a;
    asm("{ .reg .u64 t; cvta.to.shared.u64 t, %1; cvt.u32.u64 %0, t; }" : "=r"(a) : "l"(p));
    return a;
}
static __device__ __forceinline__ uint32_t cvt2(float hi, float lo) {
    uint32_t r;
    asm("cvt.rn.bf16x2.f32 %0, %1, %2;" : "=r"(r) : "f"(hi), "f"(lo));
    return r;
}
static __device__ __forceinline__ void cp16(uint32_t dst, const void* src) {
    asm volatile("cp.async.cg.shared.global [%0], [%1], 16;" :: "r"(dst), "l"(src));
}
#define CP_COMMIT() asm volatile("cp.async.commit_group;" ::: "memory")
#define CP_WAIT0()  asm volatile("cp.async.wait_group 0;" ::: "memory")
#define CP_WAIT1()  asm volatile("cp.async.wait_group 1;" ::: "memory")
#define CP_WAIT2()  asm volatile("cp.async.wait_group 2;" ::: "memory")

#define LDMX4(r, a) \
    asm volatile("ldmatrix.sync.aligned.m8n8.x4.shared.b16 {%0,%1,%2,%3}, [%4];" \
        : "=r"((r)[0]), "=r"((r)[1]), "=r"((r)[2]), "=r"((r)[3]) : "r"(a))
#define LDMX4T(r, a) \
    asm volatile("ldmatrix.sync.aligned.m8n8.x4.trans.shared.b16 {%0,%1,%2,%3}, [%4];" \
        : "=r"((r)[0]), "=r"((r)[1]), "=r"((r)[2]), "=r"((r)[3]) : "r"(a))
#define MMA16816(c, a, b0, b1) \
    asm volatile("mma.sync.aligned.m16n8k16.row.col.f32.bf16.bf16.f32 " \
        "{%0,%1,%2,%3},{%4,%5,%6,%7},{%8,%9},{%0,%1,%2,%3};" \
        : "+f"((c)[0]), "+f"((c)[1]), "+f"((c)[2]), "+f"((c)[3]) \
        : "r"((a)[0]), "r"((a)[1]), "r"((a)[2]), "r"((a)[3]), "r"(b0), "r"(b1))

// ---------------- prep: weights -> bf16 hi/lo split images, KC=32 chunks ----------------
__global__ void prep_b_kernel(const float* __restrict__ wkv, const float* __restrict__ wgate,
                              int nchunks) {
    int idx = blockIdx.x * blockDim.x + threadIdx.x;
    if (idx >= nchunks * 32 * 64) return;
    int n4 = idx & 63;           // group of 4 n-columns (n = n4*4, 0..255)
    int k  = (idx >> 6) & 31;    // k within chunk
    int c  = idx >> 11;          // chunk
    int kg = c * KC + k;
    int n  = n4 * 4;
    const float* w = (n < 128) ? (wkv + (size_t)kg * 128 + n)
                               : (wgate + (size_t)kg * 128 + (n - 128));
    float x0 = w[0], x1 = w[1], x2 = w[2], x3 = w[3];
    uint32_t h0 = cvt2(x1, x0), h1 = cvt2(x3, x2);
    float r0 = x0 - __uint_as_float(h0 << 16);
    float r1 = x1 - __uint_as_float(h0 & 0xFFFF0000u);
    float r2 = x2 - __uint_as_float(h1 << 16);
    float r3 = x3 - __uint_as_float(h1 & 0xFFFF0000u);
    uint32_t l0 = cvt2(r1, r0), l1 = cvt2(r3, r2);
    size_t off = (size_t)c * BCHUNK + (size_t)k * 512 + (size_t)n4 * 8;
    *(uint2*)(g_Bpre + off) = make_uint2(h0, h1);
    *(uint2*)(g_Bpre + (size_t)nchunks * BCHUNK + off) = make_uint2(l0, l1);
}

// ---------------- main fused kernel ----------------
__global__ void __launch_bounds__(NTHREADS, 1)
hca_mma_kernel(const float* __restrict__ hs,
               const int*   __restrict__ pos_ids,
               const float* __restrict__ bias,
               const float* __restrict__ norm_w,
               float*       __restrict__ out,
               int H, int nchunks)
{
    extern __shared__ __align__(16) unsigned char sm[];
    const uint32_t smb = smem_u32(sm);

    const int tid   = threadIdx.x;
    const int wid   = tid >> 5;
    const int lane  = tid & 31;
    const int mwarp = wid >> 2;   // 0..1 -> rows mwarp*64
    const int nwarp = wid & 3;    // 0..3 -> cols nwarp*64

    const float* hblk = hs + (size_t)blockIdx.x * 128 * (size_t)H;
    const size_t bLoOff = (size_t)nchunks * BCHUNK;

    // A raw chunk (128x32 f32 = 16KB): 1024 16B units, 4/thread, linear dst
    #define ISSUE_A(c_, s_) do { \
        const int k0_ = (c_) * KC; \
        _Pragma("unroll") \
        for (int i_ = 0; i_ < 4; ++i_) { \
            int u_ = tid + i_ * NTHREADS; \
            int row_ = u_ >> 3, jb_ = u_ & 7; \
            cp16(smb + ARAW + (s_) * ACHUNK + u_ * 16, \
                 hblk + (size_t)row_ * H + k0_ + jb_ * 4); \
        } \
    } while (0)
    // B chunk: per split 1024 16B units (32 rows x 512B), swizzle at dst
    #define ISSUE_B(c_, s_) do { \
        _Pragma("unroll") \
        for (int i_ = 0; i_ < 4; ++i_) { \
            int u_ = tid + i_ * NTHREADS; \
            int k_ = u_ >> 5, j_ = u_ & 31; \
            uint32_t doff_ = (uint32_t)k_ * 512 + (uint32_t)((j_ ^ (k_ & 7)) << 4); \
            const unsigned char* sH_ = g_Bpre + (size_t)(c_) * BCHUNK + (size_t)u_ * 16; \
            cp16(smb + BST + (s_) * 32768 + doff_, sH_); \
            cp16(smb + BST + (s_) * 32768 + 16384 + doff_, sH_ + bLoOff); \
        } \
    } while (0)
    // Split-convert one quarter (i_) of next chunk's raw A into tile stage.
    // A-tile swizzle (64B rows, 4x16B units): off = r*64 + ((jb16 ^ ((r>>1)&3))<<4) (+8 for odd half)
    #define CONV(i_, rs_, dst_) do { \
        int u_ = tid + (i_) * NTHREADS; \
        int row_ = u_ >> 3, jb_ = u_ & 7; \
        float4 x_ = *(const float4*)(sm + ARAW + (rs_) * ACHUNK + (size_t)u_ * 16); \
        uint32_t h0_ = cvt2(x_.y, x_.x), h1_ = cvt2(x_.w, x_.z); \
        float r0_ = x_.x - __uint_as_float(h0_ << 16); \
        float r1_ = x_.y - __uint_as_float(h0_ & 0xFFFF0000u); \
        float r2_ = x_.z - __uint_as_float(h1_ << 16); \
        float r3_ = x_.w - __uint_as_float(h1_ & 0xFFFF0000u); \
        uint32_t l0_ = cvt2(r1_, r0_), l1_ = cvt2(r3_, r2_); \
        uint32_t off_ = (uint32_t)row_ * 64 \
            + ((((uint32_t)(jb_ >> 1)) ^ (((uint32_t)row_ >> 1) & 3u)) << 4) \
            + (uint32_t)(jb_ & 1) * 8; \
        *(uint2*)((dst_) + off_) = make_uint2(h0_, h1_); \
        *(uint2*)((dst_) + 8192 + off_) = make_uint2(l0_, l1_); \
    } while (0)

    // prologue: 3-deep cp.async pipeline + convert chunk 0
    ISSUE_A(0, 0); ISSUE_B(0, 0); CP_COMMIT();
    if (nchunks > 1) { ISSUE_A(1, 1); ISSUE_B(1, 1); CP_COMMIT(); }
    if (nchunks > 2) { ISSUE_A(2, 2); ISSUE_B(2, 2); CP_COMMIT(); }
    CP_WAIT2();
    __syncthreads();
    {
        unsigned char* dst0 = sm + ATIL;
        #pragma unroll
        for (int i = 0; i < 4; ++i) CONV(i, 0, dst0);
    }

    float acc[4][8][4];
    #pragma unroll
    for (int mi = 0; mi < 4; ++mi)
        #pragma unroll
        for (int ni = 0; ni < 8; ++ni)
            #pragma unroll
            for (int e = 0; e < 4; ++e) acc[mi][ni][e] = 0.f;

    // per-lane ldmatrix constants
    const uint32_t rBase = (uint32_t)(mwarp * 64) + (uint32_t)(lane & 15);
    const uint32_t keyM  = (rBase >> 1) & 3u;                    // A-tile XOR key
    const uint32_t aRowB = rBase * 64u;
    const uint32_t l4    = (uint32_t)(lane >> 4);
    const uint32_t bKlo  = (uint32_t)(lane & 15);                // k within k16 group
    const uint32_t keyB  = (uint32_t)(lane & 7);
    const uint32_t bNb   = (uint32_t)(nwarp * 8) + l4;           // 16B n-block base

    int s3 = 0;            // c % 3
    int rs = (nchunks > 1) ? 1 : 0;  // (c+1) % 3

    #pragma unroll 1
    for (int c = 0; c < nchunks; ++c) {
        const int haveNext = (c + 1 < nchunks);
        if (c + 2 < nchunks)      CP_WAIT1();   // g_{c+1} done, g_{c+2} in flight
        else if (haveNext)        CP_WAIT0();   // tail: only g_{c+1} pending
        __syncthreads();

        const uint32_t bStage = smb + BST + (uint32_t)s3 * 32768u;
        const uint32_t atB    = smb + ATIL + (uint32_t)(c & 1) * 16384u;
        unsigned char* dstT   = sm + ATIL + ((c + 1) & 1) * 16384;

        #pragma unroll
        for (int kk = 0; kk < 2; ++kk) {
            uint32_t ah[4][4], al[4][4], bh[4][4], bl[4][4];
            const uint32_t aoff = (((uint32_t)(kk * 2) + l4) ^ keyM) << 4;
            const uint32_t bRow = (uint32_t)kk * 8192u + bKlo * 512u;
            #pragma unroll
            for (int mi = 0; mi < 4; ++mi)
                LDMX4(ah[mi], atB + aRowB + (uint32_t)mi * 1024u + aoff);
            #pragma unroll
            for (int ni2 = 0; ni2 < 4; ++ni2)
                LDMX4T(bh[ni2], bStage + bRow + (((bNb + (uint32_t)ni2 * 2u) ^ keyB) << 4));
            #pragma unroll
            for (int mi = 0; mi < 4; ++mi)
                #pragma unroll
                for (int ni2 = 0; ni2 < 4; ++ni2) {
                    MMA16816(acc[mi][ni2 * 2],     ah[mi], bh[ni2][0], bh[ni2][1]);
                    MMA16816(acc[mi][ni2 * 2 + 1], ah[mi], bh[ni2][2], bh[ni2][3]);
                }
            #pragma unroll
            for (int ni2 = 0; ni2 < 4; ++ni2)
                LDMX4T(bl[ni2], bStage + 16384u + bRow + (((bNb + (uint32_t)ni2 * 2u) ^ keyB) << 4));
            #pragma unroll
            for (int mi = 0; mi < 4; ++mi)
                #pragma unroll
                for (int ni2 = 0; ni2 < 4; ++ni2) {
                    MMA16816(acc[mi][ni2 * 2],     ah[mi], bl[ni2][0], bl[ni2][1]);
                    MMA16816(acc[mi][ni2 * 2 + 1], ah[mi], bl[ni2][2], bl[ni2][3]);
                }
            #pragma unroll
            for (int mi = 0; mi < 4; ++mi)
                LDMX4(al[mi], atB + 8192u + aRowB + (uint32_t)mi * 1024u + aoff);
            #pragma unroll
            for (int mi = 0; mi < 4; ++mi)
                #pragma unroll
                for (int ni2 = 0; ni2 < 4; ++ni2) {
                    MMA16816(acc[mi][ni2 * 2],     al[mi], bh[ni2][0], bh[ni2][1]);
                    MMA16816(acc[mi][ni2 * 2 + 1], al[mi], bh[ni2][2], bh[ni2][3]);
                }
            // interleave next-chunk A convert into the MMA stream
            if (haveNext) {
                if (kk == 0) { CONV(0, rs, dstT); CONV(1, rs, dstT); }
                else         { CONV(2, rs, dstT); CONV(3, rs, dstT); }
            }
        }
        __syncthreads();
        if (c + 3 < nchunks) { ISSUE_A(c + 3, s3); ISSUE_B(c + 3, s3); CP_COMMIT(); }
        s3 = rs;
        rs = (rs + 1 == 3) ? 0 : rs + 1;
    }

    // ---------------- epilogue (identical math to round 7) ----------------
    // Dump accums to bank-swizzled smem matrix at offset 0:
    //   val(r, col) @ r*1024 + (((col>>1) ^ (r&7)) << 3) + (col&1)*4
    #pragma unroll
    for (int mi = 0; mi < 4; ++mi) {
        int row0 = mwarp * 64 + mi * 16 + (lane >> 2);
        int row1 = row0 + 8;
        #pragma unroll
        for (int ni = 0; ni < 8; ++ni) {
            int pair = nwarp * 32 + ni * 4 + (lane & 3);
            *(float2*)(sm + row0 * 1024 + ((pair ^ (row0 & 7)) << 3)) =
                make_float2(acc[mi][ni][0], acc[mi][ni][1]);
            *(float2*)(sm + row1 * 1024 + ((pair ^ (row1 & 7)) << 3)) =
                make_float2(acc[mi][ni][2], acc[mi][ni][3]);
        }
    }
    __syncthreads();

    {
        const int d = tid & 127, half = tid >> 7;
        float s1 = 0.f, s2 = 0.f;
        #pragma unroll 8
        for (int ri = 0; ri < 64; ++ri) {
            int r = half * 64 + ri;
            float kv = *(const float*)(sm + r * 1024 + ((((d >> 1)      ) ^ (r & 7)) << 3) + (d & 1) * 4);
            float gv = *(const float*)(sm + r * 1024 + (((64 + (d >> 1)) ^ (r & 7)) << 3) + (d & 1) * 4);
            float g = gv + __ldg(&bias[r * 128 + d]);
            float e = expf(g);
            s1 += e;
            s2 += e * kv;
        }
        ((float*)(sm + EP_P1))[half * 128 + d] = s1;
        ((float*)(sm + EP_P2))[half * 128 + d] = s2;
    }
    __syncthreads();

    if (tid < 128) {
        float* P1 = (float*)(sm + EP_P1);
        float* P2 = (float*)(sm + EP_P2);
        float s1 = P1[tid] + P1[128 + tid];
        float s2 = P2[tid] + P2[128 + tid];
        float comp = s2 / s1;
        ((float*)(sm + EP_COMP))[tid] = comp;
        float ss = comp * comp;
        #pragma unroll
        for (int o = 16; o > 0; o >>= 1) ss += __shfl_xor_sync(0xffffffffu, ss, o);
        if (lane == 0) ((float*)(sm + EP_SSW))[wid] = ss;
    }
    __syncthreads();
    if (tid < 128) {
        float* SSW = (float*)(sm + EP_SSW);
        float tot = SSW[0] + SSW[1] + SSW[2] + SSW[3];
        float inv = rsqrtf(tot * (1.0f / 128.0f) + 1e-6f);
        ((float*)(sm + EP_CN))[tid] = ((float*)(sm + EP_COMP))[tid] * inv * __ldg(&norm_w[tid]);
    }
    __syncthreads();
    if (tid < 128) {
        const float* CN = (const float*)(sm + EP_CN);
        const int d = tid;
        float o;
        if (d < 64) {
            o = CN[d];
        } else {
            int jj = d - 64;
            int ii = jj >> 1;
            float posf = (float)__ldg(&pos_ids[(size_t)blockIdx.x * 128]);
            double pw  = pow(10000.0, (double)ii * (1.0 / 32.0));
            float invf = 1.0f / (float)pw;
            float freq = posf * invf;
            double a   = (double)freq;
            float cs = (float)cos(a);
            float sn = (float)sin(a);
            float r  = CN[d];
            float rh = (jj < 32) ? -CN[d + 32] : CN[d - 32];
            o = r * cs + rh * sn;
        }
        out[(size_t)blockIdx.x * 128 + d] = o;
    }
}

extern "C" void kernel_launch(void* const* d_in, const int* in_sizes, int n_in,
                              void* d_out, int out_size) {
    (void)n_in;
    const float* hs   = (const float*)d_in[0];   // hidden_states (B,S,H) f32
    const int*   pid  = (const int*)  d_in[2];   // position_ids (B,S) i32
    const float* wkv  = (const float*)d_in[3];   // (H,128)
    const float* wgt  = (const float*)d_in[4];   // (H,128)
    const float* bias = (const float*)d_in[5];   // (128,128)
    const float* nw   = (const float*)d_in[6];   // (128,)
    float* out = (float*)d_out;

    int H       = in_sizes[3] / 128;             // 2048
    int nchunks = H / KC;                        // 64
    int nblk    = out_size / 128;                // B*T = 128

    int prep_total = nchunks * 32 * 64;
    prep_b_kernel<<<(prep_total + 255) / 256, 256>>>(wkv, wgt, nchunks);

    cudaFuncSetAttribute(hca_mma_kernel, cudaFuncAttributeMaxDynamicSharedMemorySize, SMEM_TOTAL);
    hca_mma_kernel<<<nblk, NTHREADS, SMEM_TOTAL>>>(hs, pid, bias, nw, out, H, nchunks);
}